// round 8
// baseline (speedup 1.0000x reference)
#include <cuda_runtime.h>
#include <math.h>

// EmbeddingToExpression: per-region MLP 16 -> 5 (exact-erf GELU) -> 1
//   R=1024, C=8192, DIN=16, E=5, NREG=2048. out[c,r] f32.
//
// R8 = R7 (cp.async DEPTH-4 ring, warp-per-region, grid region-fast,
// hoisted swizzle offsets, GELU const folding) + packed f32x2 MLP:
//   - accumulate over i-PAIRS with fma.rn.f32x2: x-pairs come free as
//     aligned reg pairs from LDS.128 (read stage tile as ulonglong2);
//     80 FFMA -> 40 FFMA2 + 5 unpack + 5 FADD per cell.
//   - weights repacked once per block into (w[2j][e], w[2j+1][e]) pairs
//     via scalar LDG + mov.b64 (no prologue register spike).
//   - cp.async prologue issued BEFORE weight setup (earlier DRAM start).

#define RR      1024
#define CC      8192
#define DIN     16
#define EE      5
#define CPB     256          // cells per block
#define RPB     4            // regions per block (one warp each)
#define PASSES  8            // CPB / 32
#define DEPTH   4            // pipeline ring depth
#define STAGE_B 2048         // 32 cells * 64 B per warp-pass

typedef unsigned long long ull;

__device__ __forceinline__ unsigned sw128(unsigned o) {
    return o ^ ((o >> 3) & 0x70);
}
__device__ __forceinline__ void cp16(unsigned dst, const void* src) {
    asm volatile("cp.async.cg.shared.global [%0], [%1], 16;\n"
                 :: "r"(dst), "l"(src));
}
__device__ __forceinline__ void cp_commit() {
    asm volatile("cp.async.commit_group;\n" ::: "memory");
}
__device__ __forceinline__ void cp_wait3() {
    asm volatile("cp.async.wait_group 3;\n" ::: "memory");
}

#define FMA2(d, a, b, c) \
    asm("fma.rn.f32x2 %0, %1, %2, %3;" : "=l"(d) : "l"(a), "l"(b), "l"(c))
#define PACK2(d, lo, hi) \
    asm("mov.b64 %0, {%1, %2};" : "=l"(d) : "f"(lo), "f"(hi))
#define UNPK2(lo, hi, p) \
    asm("mov.b64 {%0, %1}, %2;" : "=f"(lo), "=f"(hi) : "l"(p))

__global__ __launch_bounds__(128, 4)
void e2e_kernel(const float* __restrict__ emb,
                const void*  __restrict__ oi,     // int32 or int64, detected
                const float* __restrict__ W1,     // [NREG, DIN, E]
                const float* __restrict__ b1,     // [NREG, E]
                const float* __restrict__ Wf,     // [NREG, E, 1]
                float* __restrict__ out)          // [C, R]
{
    __shared__ __align__(1024) char s_stage[RPB * DEPTH * STAGE_B]; // 32 KB
    __shared__ float s_out[RPB * CPB];                              // 4 KB
    __shared__ int   s_is64;

    // Detect regions_oi width (values < 2048 => int64 high words are 0).
    if (threadIdx.x == 0) {
        const int* w = (const int*)oi;
        int all0 = 1;
        #pragma unroll
        for (int k = 0; k < 32; k++) all0 &= (w[2 * k + 1] == 0);
        s_is64 = all0;
    }
    __syncthreads();

    const int warp = threadIdx.x >> 5;
    const int lane = threadIdx.x & 31;
    const int r    = blockIdx.x * RPB + warp;   // region group = FAST grid dim
    const int c0   = blockIdx.y * CPB;

    int reg;
    if (s_is64) reg = (int)((const long long*)oi)[r];
    else        reg = ((const int*)oi)[r];

    // ---- hoisted swizzled offsets + pipeline bases ----
    const char* gsrc = (const char*)(emb + ((size_t)r * CC + c0) * DIN);
    char*       wbuf = s_stage + warp * (DEPTH * STAGE_B);
    const unsigned sbase = (unsigned)__cvta_generic_to_shared(wbuf);
    unsigned po[4], co[4];
    #pragma unroll
    for (int k = 0; k < 4; k++) {
        po[k] = sw128(k * 512 + lane * 16);     // producer dst offsets
        co[k] = sw128(lane * 64 + k * 16);      // consumer src offsets
    }
    const unsigned goff = lane * 16;

    // ---- start DRAM traffic first: prologue passes 0..2 as groups 0..2 ----
    #pragma unroll
    for (int g = 0; g < DEPTH - 1; g++) {
        const unsigned slot = sbase + (g % DEPTH) * STAGE_B;
        const char* s = gsrc + g * STAGE_B + goff;
        cp16(slot + po[0], s);
        cp16(slot + po[1], s + 512);
        cp16(slot + po[2], s + 1024);
        cp16(slot + po[3], s + 1536);
        cp_commit();
    }

    // ---- weights: packed i-pairs (w[2j][e], w[2j+1][e]) * (1/sqrt2) ----
    const float KI = 0.70710678118654752f;      // 1/sqrt(2)
    const float KQ = 0.70710678118654752f;      // 0.5/KI
    const float* wrow = W1 + (size_t)reg * (DIN * EE);
    ull wpk[(DIN / 2) * EE];                    // 40 pairs = 80 regs
    #pragma unroll
    for (int j = 0; j < DIN / 2; j++) {
        #pragma unroll
        for (int e = 0; e < EE; e++) {
            float a = wrow[(2 * j) * EE + e] * KI;
            float b = wrow[(2 * j + 1) * EE + e] * KI;
            PACK2(wpk[j * EE + e], a, b);
        }
    }
    ull  bbp[EE];
    float wq[EE];
    #pragma unroll
    for (int e = 0; e < EE; e++) {
        PACK2(bbp[e], b1[reg * EE + e] * KI, 0.0f);
        wq[e] = Wf[reg * EE + e] * KQ;
    }

    #pragma unroll
    for (int p = 0; p < PASSES; p++) {
        const int g = p + DEPTH - 1;
        if (g < PASSES) {
            const unsigned slot = sbase + (g % DEPTH) * STAGE_B;
            const char* s = gsrc + g * STAGE_B + goff;
            cp16(slot + po[0], s);
            cp16(slot + po[1], s + 512);
            cp16(slot + po[2], s + 1024);
            cp16(slot + po[3], s + 1536);
        }
        cp_commit();
        cp_wait3();   // all but newest 3 groups done => pass p landed

        // ---- compute pass p: x-pairs direct from LDS.128 reg pairs ----
        const char* xb = wbuf + (p % DEPTH) * STAGE_B;
        ulonglong2 q0 = *(const ulonglong2*)(xb + co[0]);
        ulonglong2 q1 = *(const ulonglong2*)(xb + co[1]);
        ulonglong2 q2 = *(const ulonglong2*)(xb + co[2]);
        ulonglong2 q3 = *(const ulonglong2*)(xb + co[3]);

        ull a0 = bbp[0], a1 = bbp[1], a2 = bbp[2], a3 = bbp[3], a4 = bbp[4];
        #define ACCP(XP, J) \
            FMA2(a0, (XP), wpk[(J) * EE + 0], a0); \
            FMA2(a1, (XP), wpk[(J) * EE + 1], a1); \
            FMA2(a2, (XP), wpk[(J) * EE + 2], a2); \
            FMA2(a3, (XP), wpk[(J) * EE + 3], a3); \
            FMA2(a4, (XP), wpk[(J) * EE + 4], a4);
        ACCP(q0.x, 0)  ACCP(q0.y, 1)
        ACCP(q1.x, 2)  ACCP(q1.y, 3)
        ACCP(q2.x, 4)  ACCP(q2.y, 5)
        ACCP(q3.x, 6)  ACCP(q3.y, 7)
        #undef ACCP

        float h0, h1, h2, h3, h4, t;
        UNPK2(h0, t, a0);  h0 += t;
        UNPK2(h1, t, a1);  h1 += t;
        UNPK2(h2, t, a2);  h2 += t;
        UNPK2(h3, t, a3);  h3 += t;
        UNPK2(h4, t, a4);  h4 += t;

        // gelu(h)*wf == h' * (1 + erf(h')) * (0.5/KI)*wf,  h' = h/sqrt(2)
        float e0 = 1.0f + erff(h0);
        float e1 = 1.0f + erff(h1);
        float e2 = 1.0f + erff(h2);
        float e3 = 1.0f + erff(h3);
        float e4 = 1.0f + erff(h4);
        float acc = (h0 * wq[0]) * e0;
        acc = fmaf(h1 * wq[1], e1, acc);
        acc = fmaf(h2 * wq[2], e2, acc);
        acc = fmaf(h3 * wq[3], e3, acc);
        acc = fmaf(h4 * wq[4], e4, acc);

        s_out[warp * CPB + (p * 32 + lane)] = acc;
    }
    __syncthreads();

    // ---- transposed write: 16B per thread-cell; adjacent blockIdx.x
    //      supplies the neighboring half-sector -> L2 write-merge.
    #pragma unroll
    for (int cc = 0; cc < CPB; cc += 128) {
        const int c = cc + threadIdx.x;
        float4 o;
        o.x = s_out[0 * CPB + c];
        o.y = s_out[1 * CPB + c];
        o.z = s_out[2 * CPB + c];
        o.w = s_out[3 * CPB + c];
        float* op = out + (size_t)(c0 + c) * RR + (size_t)blockIdx.x * RPB;
        *(float4*)op = o;
    }
}

extern "C" void kernel_launch(void* const* d_in, const int* in_sizes, int n_in,
                              void* d_out, int out_size)
{
    const float* emb = (const float*)d_in[0];   // [R, C, DIN] f32
    const void*  oi  = d_in[1];                 // [R] int32/int64
    const float* W1  = (const float*)d_in[2];   // [NREG, DIN, E]
    const float* b1  = (const float*)d_in[3];   // [NREG, E]
    const float* Wf  = (const float*)d_in[4];   // [NREG, E, 1]
    float* out = (float*)d_out;                 // [C, R]

    dim3 grid(RR / RPB, CC / CPB);              // (256, 32) region-group fast
    e2e_kernel<<<grid, 128>>>(emb, oi, W1, b1, Wf, out);
}

// round 9
// speedup vs baseline: 1.0392x; 1.0392x over previous
#include <cuda_runtime.h>
#include <math.h>

// EmbeddingToExpression: per-region MLP 16 -> 5 (exact-erf GELU) -> 1
//   R=1024, C=8192, DIN=16, E=5, NREG=2048. out[c,r] f32.
//
// R9 = R7 (cp.async ring, warp-per-region, grid region-fast, hoisted
// swizzle, GELU const folding; FFMA2 of R8 reverted - it raised alu%) +
//  - erff replaced by branchless Abramowitz-Stegun 7.1.26 (abs err
//    1.5e-7): t=1/(1+p|x|), erf=1-poly(t)*exp(-x^2). ~12 instrs w/ 2
//    MUFU (RCP, EX2) vs ~20-25 for erff; offloads fma/alu pipes.
//  - DEPTH 5 / wait_group 4: 45 KB static SMEM, smoother DRAM demand.

#define RR      1024
#define CC      8192
#define DIN     16
#define EE      5
#define CPB     256          // cells per block
#define RPB     4            // regions per block (one warp each)
#define PASSES  8            // CPB / 32
#define DEPTH   5            // pipeline ring depth
#define STAGE_B 2048         // 32 cells * 64 B per warp-pass

__device__ __forceinline__ unsigned sw128(unsigned o) {
    return o ^ ((o >> 3) & 0x70);
}
__device__ __forceinline__ void cp16(unsigned dst, const void* src) {
    asm volatile("cp.async.cg.shared.global [%0], [%1], 16;\n"
                 :: "r"(dst), "l"(src));
}
__device__ __forceinline__ void cp_commit() {
    asm volatile("cp.async.commit_group;\n" ::: "memory");
}
__device__ __forceinline__ void cp_wait4() {
    asm volatile("cp.async.wait_group 4;\n" ::: "memory");
}

// 1 + erf(x), branchless. Abramowitz-Stegun 7.1.26, |abs err| <= 1.5e-7.
// Tails exact via exp underflow: x<<0 -> 0, x>>0 -> 2.
__device__ __forceinline__ float erf1p(float x) {
    const float p  = 0.3275911f;
    const float a1 = 0.254829592f, a2 = -0.284496736f, a3 = 1.421413741f;
    const float a4 = -1.453152027f, a5 = 1.061405429f;
    float ax = fabsf(x);
    float t  = __fdividef(1.0f, fmaf(p, ax, 1.0f));   // MUFU.RCP path
    float r  = fmaf(a5, t, a4);
    r = fmaf(r, t, a3);
    r = fmaf(r, t, a2);
    r = fmaf(r, t, a1);
    r = r * t;
    float u = r * __expf(-x * x);                     // MUFU.EX2 path
    return 1.0f + copysignf(1.0f - u, x);
}

__global__ __launch_bounds__(128, 4)
void e2e_kernel(const float* __restrict__ emb,
                const void*  __restrict__ oi,     // int32 or int64, detected
                const float* __restrict__ W1,     // [NREG, DIN, E]
                const float* __restrict__ b1,     // [NREG, E]
                const float* __restrict__ Wf,     // [NREG, E, 1]
                float* __restrict__ out)          // [C, R]
{
    __shared__ __align__(1024) char s_stage[RPB * DEPTH * STAGE_B]; // 40 KB
    __shared__ float s_out[RPB * CPB];                              // 4 KB
    __shared__ int   s_is64;

    // Detect regions_oi width (values < 2048 => int64 high words are 0).
    if (threadIdx.x == 0) {
        const int* w = (const int*)oi;
        int all0 = 1;
        #pragma unroll
        for (int k = 0; k < 32; k++) all0 &= (w[2 * k + 1] == 0);
        s_is64 = all0;
    }
    __syncthreads();

    const int warp = threadIdx.x >> 5;
    const int lane = threadIdx.x & 31;
    const int r    = blockIdx.x * RPB + warp;   // region group = FAST grid dim
    const int c0   = blockIdx.y * CPB;

    int reg;
    if (s_is64) reg = (int)((const long long*)oi)[r];
    else        reg = ((const int*)oi)[r];

    // ---- hoisted swizzled offsets + pipeline bases ----
    const char* gsrc = (const char*)(emb + ((size_t)r * CC + c0) * DIN);
    char*       wbuf = s_stage + warp * (DEPTH * STAGE_B);
    const unsigned sbase = (unsigned)__cvta_generic_to_shared(wbuf);
    unsigned po[4], co[4];
    #pragma unroll
    for (int k = 0; k < 4; k++) {
        po[k] = sw128(k * 512 + lane * 16);     // producer dst offsets
        co[k] = sw128(lane * 64 + k * 16);      // consumer src offsets
    }
    const unsigned goff = lane * 16;

    // ---- start DRAM traffic first: prologue passes 0..3 as groups 0..3 ----
    #pragma unroll
    for (int g = 0; g < DEPTH - 1; g++) {
        const unsigned slot = sbase + (g % DEPTH) * STAGE_B;
        const char* s = gsrc + g * STAGE_B + goff;
        cp16(slot + po[0], s);
        cp16(slot + po[1], s + 512);
        cp16(slot + po[2], s + 1024);
        cp16(slot + po[3], s + 1536);
        cp_commit();
    }

    // ---- weights, prescaled by 1/sqrt(2) so h' = h/sqrt(2) ----
    const float KI = 0.70710678118654752f;      // 1/sqrt(2)
    const float KQ = 0.70710678118654752f;      // 0.5/KI
    float w[DIN * EE];
    {
        const float4* wp = (const float4*)(W1 + (size_t)reg * (DIN * EE));
        #pragma unroll
        for (int q = 0; q < (DIN * EE) / 4; q++) {
            float4 v = wp[q];
            w[4 * q + 0] = v.x * KI; w[4 * q + 1] = v.y * KI;
            w[4 * q + 2] = v.z * KI; w[4 * q + 3] = v.w * KI;
        }
    }
    float bb[EE], wq[EE];
    #pragma unroll
    for (int e = 0; e < EE; e++) {
        bb[e] = b1[reg * EE + e] * KI;
        wq[e] = Wf[reg * EE + e] * KQ;          // 0.5/KI * wf
    }

    #pragma unroll
    for (int p = 0; p < PASSES; p++) {
        const int g = p + DEPTH - 1;
        if (g < PASSES) {
            const unsigned slot = sbase + (g % DEPTH) * STAGE_B;
            const char* s = gsrc + g * STAGE_B + goff;
            cp16(slot + po[0], s);
            cp16(slot + po[1], s + 512);
            cp16(slot + po[2], s + 1024);
            cp16(slot + po[3], s + 1536);
        }
        cp_commit();
        cp_wait4();   // all but newest 4 groups done => pass p landed

        // ---- compute pass p from SMEM (conflict-free LDS.128) ----
        const char* xb = wbuf + (p % DEPTH) * STAGE_B;
        float4 v0 = *(const float4*)(xb + co[0]);
        float4 v1 = *(const float4*)(xb + co[1]);
        float4 v2 = *(const float4*)(xb + co[2]);
        float4 v3 = *(const float4*)(xb + co[3]);

        float h0 = bb[0], h1 = bb[1], h2 = bb[2], h3 = bb[3], h4 = bb[4];
        #define ACC(V, I) \
            h0 = fmaf((V), w[(I) * EE + 0], h0); \
            h1 = fmaf((V), w[(I) * EE + 1], h1); \
            h2 = fmaf((V), w[(I) * EE + 2], h2); \
            h3 = fmaf((V), w[(I) * EE + 3], h3); \
            h4 = fmaf((V), w[(I) * EE + 4], h4);
        ACC(v0.x, 0)  ACC(v0.y, 1)  ACC(v0.z, 2)  ACC(v0.w, 3)
        ACC(v1.x, 4)  ACC(v1.y, 5)  ACC(v1.z, 6)  ACC(v1.w, 7)
        ACC(v2.x, 8)  ACC(v2.y, 9)  ACC(v2.z,10)  ACC(v2.w,11)
        ACC(v3.x,12)  ACC(v3.y,13)  ACC(v3.z,14)  ACC(v3.w,15)
        #undef ACC

        // gelu(h)*wf == h' * (1 + erf(h')) * (0.5/KI)*wf,  h' = h/sqrt(2)
        float q0 = erf1p(h0);
        float q1 = erf1p(h1);
        float q2 = erf1p(h2);
        float q3 = erf1p(h3);
        float q4 = erf1p(h4);
        float acc = (h0 * wq[0]) * q0;
        acc = fmaf(h1 * wq[1], q1, acc);
        acc = fmaf(h2 * wq[2], q2, acc);
        acc = fmaf(h3 * wq[3], q3, acc);
        acc = fmaf(h4 * wq[4], q4, acc);

        s_out[warp * CPB + (p * 32 + lane)] = acc;
    }
    __syncthreads();

    // ---- transposed write: 16B per thread-cell; adjacent blockIdx.x
    //      supplies the neighboring half-sector -> L2 write-merge.
    #pragma unroll
    for (int cc = 0; cc < CPB; cc += 128) {
        const int c = cc + threadIdx.x;
        float4 o;
        o.x = s_out[0 * CPB + c];
        o.y = s_out[1 * CPB + c];
        o.z = s_out[2 * CPB + c];
        o.w = s_out[3 * CPB + c];
        float* op = out + (size_t)(c0 + c) * RR + (size_t)blockIdx.x * RPB;
        *(float4*)op = o;
    }
}

extern "C" void kernel_launch(void* const* d_in, const int* in_sizes, int n_in,
                              void* d_out, int out_size)
{
    const float* emb = (const float*)d_in[0];   // [R, C, DIN] f32
    const void*  oi  = d_in[1];                 // [R] int32/int64
    const float* W1  = (const float*)d_in[2];   // [NREG, DIN, E]
    const float* b1  = (const float*)d_in[3];   // [NREG, E]
    const float* Wf  = (const float*)d_in[4];   // [NREG, E, 1]
    float* out = (float*)d_out;                 // [C, R]

    dim3 grid(RR / RPB, CC / CPB);              // (256, 32) region-group fast
    e2e_kernel<<<grid, 128>>>(emb, oi, W1, b1, Wf, out);
}